// round 12
// baseline (speedup 1.0000x reference)
#include <cuda_runtime.h>
#include <cstdint>

// ComplexScaling: separable bilinear grid_sample, affine = s*I with s = 1 + theta[0].
// input/output: [N=32, H=1024, W=1024, C=2] fp32 NHWC.
//
// Single kernel, uniform branch on broadcast scalar s = 1 + theta[0]:
//  - s == 1: exact identity map in fp32 -> persistent streaming copy.
//    Block-tiled COALESCED layout (thread accesses stride by THREADS, so each
//    warp LDG.128/STG.128 is exactly 4 x 128B lines), 4x float4 per iteration,
//    grid-stride over chunks with a fixed 1184-block grid (148 SMs x 8 blocks)
//    to eliminate the partial-wave tail of a 13.84-wave launch.
//  - s != 1: grid-stride bilinear grid-sample, 4 px/thread (correct for any theta).

static constexpr int N_ = 32;
static constexpr int H_ = 1024;
static constexpr int W_ = 1024;
static constexpr int LOG_W = 10;
static constexpr int LOG_HW = 20;
static constexpr int TOTAL_PIX = N_ * H_ * W_;                 // 33,554,432
static constexpr int TOTAL_V4  = TOTAL_PIX / 2;                // 16,777,216 float4

static constexpr int THREADS = 256;
static constexpr int BLOCKS  = 148 * 8;                        // 1184 persistent blocks
static constexpr int V4_PER_ITER = 4;                          // 64 B/thread/iter
static constexpr int CHUNK_V4 = THREADS * V4_PER_ITER;         // 1024 float4 per chunk
static constexpr int NCHUNKS_COPY = TOTAL_V4 / CHUNK_V4;       // 16384 chunks
static constexpr int PIX_PER_THREAD = 4;                       // general path

__global__ __launch_bounds__(THREADS, 8)
void complex_scaling_kernel(const float2* __restrict__ in,
                            const float* __restrict__ theta,
                            float2* __restrict__ out)
{
    const float s = 1.0f + __ldg(theta);

    if (s == 1.0f) {
        // ---- identity fast path: persistent coalesced streaming copy ----
        const float4* __restrict__ in4  = (const float4*)in;
        float4*       __restrict__ out4 = (float4*)out;
        for (int c = blockIdx.x; c < NCHUNKS_COPY; c += BLOCKS) {
            const int base = c * CHUNK_V4 + threadIdx.x;
            float4 a0 = __ldcs(&in4[base + 0 * THREADS]);
            float4 a1 = __ldcs(&in4[base + 1 * THREADS]);
            float4 a2 = __ldcs(&in4[base + 2 * THREADS]);
            float4 a3 = __ldcs(&in4[base + 3 * THREADS]);
            __stcs(&out4[base + 0 * THREADS], a0);
            __stcs(&out4[base + 1 * THREADS], a1);
            __stcs(&out4[base + 2 * THREADS], a2);
            __stcs(&out4[base + 3 * THREADS], a3);
        }
        return;
    }

    // ---- general bilinear path: grid-stride, 4 adjacent pixels per chunk ----
    const int tid = blockIdx.x * blockDim.x + threadIdx.x;
    const int stride = BLOCKS * THREADS;                       // 303,104 threads
    const int nchunks = TOTAL_PIX / PIX_PER_THREAD;            // 8,388,608

    for (int t = tid; t < nchunks; t += stride) {
        const int p0 = t * PIX_PER_THREAD;
        const int w0 = p0 & (W_ - 1);           // W divisible by 4 -> same row
        const int h  = (p0 >> LOG_W) & (H_ - 1);
        const int n  = p0 >> LOG_HW;

        // y (row) coordinate — shared by the 4 pixels
        const float yn = (2.0f * (float)h + 1.0f) * (1.0f / (float)H_) - 1.0f;
        const float iy = ((s * yn + 1.0f) * (float)H_ - 1.0f) * 0.5f;
        const float y0f = floorf(iy);
        float wy1 = iy - y0f, wy0 = 1.0f - wy1;
        const int y0 = (int)y0f, y1 = y0 + 1;
        if (y0 < 0 || y0 > H_ - 1) wy0 = 0.0f;
        if (y1 < 0 || y1 > H_ - 1) wy1 = 0.0f;
        const int cy0 = min(max(y0, 0), H_ - 1);
        const int cy1 = min(max(y1, 0), H_ - 1);

        const float2* __restrict__ base  = in + ((size_t)n << LOG_HW);
        const float2* __restrict__ row0p = base + ((size_t)cy0 << LOG_W);
        const float2* __restrict__ row1p = base + ((size_t)cy1 << LOG_W);

        float2 res[PIX_PER_THREAD];

#pragma unroll
        for (int k = 0; k < PIX_PER_THREAD; ++k) {
            const int w = w0 + k;
            const float xn = (2.0f * (float)w + 1.0f) * (1.0f / (float)W_) - 1.0f;
            const float ix = ((s * xn + 1.0f) * (float)W_ - 1.0f) * 0.5f;
            const float x0f = floorf(ix);
            float wx1 = ix - x0f, wx0 = 1.0f - wx1;
            const int x0 = (int)x0f, x1 = x0 + 1;
            if (x0 < 0 || x0 > W_ - 1) wx0 = 0.0f;
            if (x1 < 0 || x1 > W_ - 1) wx1 = 0.0f;
            const int cx0 = min(max(x0, 0), W_ - 1);
            const int cx1 = min(max(x1, 0), W_ - 1);

            const float2 v00 = __ldg(&row0p[cx0]);
            const float2 v01 = __ldg(&row0p[cx1]);
            const float2 v10 = __ldg(&row1p[cx0]);
            const float2 v11 = __ldg(&row1p[cx1]);

            const float row0x = wx0 * v00.x + wx1 * v01.x;
            const float row0y = wx0 * v00.y + wx1 * v01.y;
            const float row1x = wx0 * v10.x + wx1 * v11.x;
            const float row1y = wx0 * v10.y + wx1 * v11.y;
            res[k].x = wy0 * row0x + wy1 * row1x;
            res[k].y = wy0 * row0y + wy1 * row1y;
        }

        float4* __restrict__ outv = (float4*)(out + p0);
        outv[0] = make_float4(res[0].x, res[0].y, res[1].x, res[1].y);
        outv[1] = make_float4(res[2].x, res[2].y, res[3].x, res[3].y);
    }
}

extern "C" void kernel_launch(void* const* d_in, const int* in_sizes, int n_in,
                              void* d_out, int out_size)
{
    const float2* in    = (const float2*)d_in[0];
    const float*  theta = (const float*)d_in[1];
    float2*       out   = (float2*)d_out;

    complex_scaling_kernel<<<BLOCKS, THREADS>>>(in, theta, out);
}

// round 13
// speedup vs baseline: 1.1257x; 1.1257x over previous
#include <cuda_runtime.h>
#include <cstdint>

// ComplexScaling: separable bilinear grid_sample, affine = s*I with s = 1 + theta[0].
// input/output: [N=32, H=1024, W=1024, C=2] fp32 NHWC.
//
// Single kernel, uniform branch on broadcast scalar s = 1 + theta[0]:
//  - s == 1: exact identity map in fp32 -> streaming copy. COALESCED block-tiled
//    layout: thread reads in4[base + k*THREADS], so each warp LDG.128 covers 32
//    consecutive lanes x 16B = exactly 4 x 128B lines (1x L1tex line
//    amplification). 4x float4/thread, evict-first hints. Measured at the
//    DRAM plateau (~6.4 TB/s bidirectional, 80% of spec) — converged config.
//  - s != 1: grid-stride bilinear grid-sample, 4 px/thread (correct for any theta).

static constexpr int N_ = 32;
static constexpr int H_ = 1024;
static constexpr int W_ = 1024;
static constexpr int LOG_W = 10;
static constexpr int LOG_HW = 20;
static constexpr int TOTAL_PIX = N_ * H_ * W_;                 // 33,554,432
static constexpr int TOTAL_V4  = TOTAL_PIX / 2;                // 16,777,216 float4

static constexpr int THREADS = 256;
static constexpr int V4_PER_THREAD = 4;                        // 64 B/thread (fast path)
static constexpr int BLOCKS = TOTAL_V4 / V4_PER_THREAD / THREADS;   // 16384
static constexpr int PIX_PER_THREAD = 4;                       // general path

__global__ __launch_bounds__(THREADS, 8)
void complex_scaling_kernel(const float2* __restrict__ in,
                            const float* __restrict__ theta,
                            float2* __restrict__ out)
{
    const float s = 1.0f + __ldg(theta);

    if (s == 1.0f) {
        // ---- identity fast path: coalesced block-tiled streaming copy ----
        // Block owns a contiguous span of THREADS*V4_PER_THREAD float4s.
        const float4* __restrict__ in4  = (const float4*)in;
        float4*       __restrict__ out4 = (float4*)out;
        const int base = blockIdx.x * (THREADS * V4_PER_THREAD) + threadIdx.x;
        float4 a0 = __ldcs(&in4[base + 0 * THREADS]);
        float4 a1 = __ldcs(&in4[base + 1 * THREADS]);
        float4 a2 = __ldcs(&in4[base + 2 * THREADS]);
        float4 a3 = __ldcs(&in4[base + 3 * THREADS]);
        __stcs(&out4[base + 0 * THREADS], a0);
        __stcs(&out4[base + 1 * THREADS], a1);
        __stcs(&out4[base + 2 * THREADS], a2);
        __stcs(&out4[base + 3 * THREADS], a3);
        return;
    }

    // ---- general bilinear path: grid-stride, 4 adjacent pixels per chunk ----
    const int tid = blockIdx.x * blockDim.x + threadIdx.x;
    const int stride = BLOCKS * THREADS;                       // 4,194,304 threads
    const int nchunks = TOTAL_PIX / PIX_PER_THREAD;            // 8,388,608

    for (int t = tid; t < nchunks; t += stride) {
        const int p0 = t * PIX_PER_THREAD;
        const int w0 = p0 & (W_ - 1);           // W divisible by 4 -> same row
        const int h  = (p0 >> LOG_W) & (H_ - 1);
        const int n  = p0 >> LOG_HW;

        // y (row) coordinate — shared by the 4 pixels
        const float yn = (2.0f * (float)h + 1.0f) * (1.0f / (float)H_) - 1.0f;
        const float iy = ((s * yn + 1.0f) * (float)H_ - 1.0f) * 0.5f;
        const float y0f = floorf(iy);
        float wy1 = iy - y0f, wy0 = 1.0f - wy1;
        const int y0 = (int)y0f, y1 = y0 + 1;
        if (y0 < 0 || y0 > H_ - 1) wy0 = 0.0f;
        if (y1 < 0 || y1 > H_ - 1) wy1 = 0.0f;
        const int cy0 = min(max(y0, 0), H_ - 1);
        const int cy1 = min(max(y1, 0), H_ - 1);

        const float2* __restrict__ base  = in + ((size_t)n << LOG_HW);
        const float2* __restrict__ row0p = base + ((size_t)cy0 << LOG_W);
        const float2* __restrict__ row1p = base + ((size_t)cy1 << LOG_W);

        float2 res[PIX_PER_THREAD];

#pragma unroll
        for (int k = 0; k < PIX_PER_THREAD; ++k) {
            const int w = w0 + k;
            const float xn = (2.0f * (float)w + 1.0f) * (1.0f / (float)W_) - 1.0f;
            const float ix = ((s * xn + 1.0f) * (float)W_ - 1.0f) * 0.5f;
            const float x0f = floorf(ix);
            float wx1 = ix - x0f, wx0 = 1.0f - wx1;
            const int x0 = (int)x0f, x1 = x0 + 1;
            if (x0 < 0 || x0 > W_ - 1) wx0 = 0.0f;
            if (x1 < 0 || x1 > W_ - 1) wx1 = 0.0f;
            const int cx0 = min(max(x0, 0), W_ - 1);
            const int cx1 = min(max(x1, 0), W_ - 1);

            const float2 v00 = __ldg(&row0p[cx0]);
            const float2 v01 = __ldg(&row0p[cx1]);
            const float2 v10 = __ldg(&row1p[cx0]);
            const float2 v11 = __ldg(&row1p[cx1]);

            const float row0x = wx0 * v00.x + wx1 * v01.x;
            const float row0y = wx0 * v00.y + wx1 * v01.y;
            const float row1x = wx0 * v10.x + wx1 * v11.x;
            const float row1y = wx0 * v10.y + wx1 * v11.y;
            res[k].x = wy0 * row0x + wy1 * row1x;
            res[k].y = wy0 * row0y + wy1 * row1y;
        }

        float4* __restrict__ outv = (float4*)(out + p0);
        outv[0] = make_float4(res[0].x, res[0].y, res[1].x, res[1].y);
        outv[1] = make_float4(res[2].x, res[2].y, res[3].x, res[3].y);
    }
}

extern "C" void kernel_launch(void* const* d_in, const int* in_sizes, int n_in,
                              void* d_out, int out_size)
{
    const float2* in    = (const float2*)d_in[0];
    const float*  theta = (const float*)d_in[1];
    float2*       out   = (float2*)d_out;

    complex_scaling_kernel<<<BLOCKS, THREADS>>>(in, theta, out);
}

// round 14
// speedup vs baseline: 1.1288x; 1.0027x over previous
#include <cuda_runtime.h>
#include <cstdint>

// ComplexScaling: separable bilinear grid_sample, affine = s*I with s = 1 + theta[0].
// input/output: [N=32, H=1024, W=1024, C=2] fp32 NHWC.
//
// CONVERGED CONFIGURATION (R9/R10/R13: 82.0 us wall, 75.5-76.0 us kernel,
// 6.33-6.38 TB/s HBM = DRAM mixed-stream plateau).
//
// Single kernel, uniform branch on broadcast scalar s = 1 + theta[0]:
//  - s == 1: exact identity map in fp32 -> streaming copy. COALESCED block-tiled
//    layout: thread accesses in4[base + k*THREADS], so each warp LDG.128/STG.128
//    covers 32 consecutive lanes x 16B = exactly 4 x 128B lines (1x L1tex line
//    amplification). 4x float4/thread (MLP=4), evict-first hints, 32 regs ->
//    full 64-warp occupancy.
//  - s != 1: grid-stride bilinear grid-sample, 4 px/thread (correct for any theta).

static constexpr int N_ = 32;
static constexpr int H_ = 1024;
static constexpr int W_ = 1024;
static constexpr int LOG_W = 10;
static constexpr int LOG_HW = 20;
static constexpr int TOTAL_PIX = N_ * H_ * W_;                 // 33,554,432
static constexpr int TOTAL_V4  = TOTAL_PIX / 2;                // 16,777,216 float4

static constexpr int THREADS = 256;
static constexpr int V4_PER_THREAD = 4;                        // 64 B/thread (fast path)
static constexpr int BLOCKS = TOTAL_V4 / V4_PER_THREAD / THREADS;   // 16384
static constexpr int PIX_PER_THREAD = 4;                       // general path

__global__ __launch_bounds__(THREADS, 8)
void complex_scaling_kernel(const float2* __restrict__ in,
                            const float* __restrict__ theta,
                            float2* __restrict__ out)
{
    const float s = 1.0f + __ldg(theta);

    if (s == 1.0f) {
        // ---- identity fast path: coalesced block-tiled streaming copy ----
        const float4* __restrict__ in4  = (const float4*)in;
        float4*       __restrict__ out4 = (float4*)out;
        const int base = blockIdx.x * (THREADS * V4_PER_THREAD) + threadIdx.x;
        float4 a0 = __ldcs(&in4[base + 0 * THREADS]);
        float4 a1 = __ldcs(&in4[base + 1 * THREADS]);
        float4 a2 = __ldcs(&in4[base + 2 * THREADS]);
        float4 a3 = __ldcs(&in4[base + 3 * THREADS]);
        __stcs(&out4[base + 0 * THREADS], a0);
        __stcs(&out4[base + 1 * THREADS], a1);
        __stcs(&out4[base + 2 * THREADS], a2);
        __stcs(&out4[base + 3 * THREADS], a3);
        return;
    }

    // ---- general bilinear path: grid-stride, 4 adjacent pixels per chunk ----
    const int tid = blockIdx.x * blockDim.x + threadIdx.x;
    const int stride = BLOCKS * THREADS;                       // 4,194,304 threads
    const int nchunks = TOTAL_PIX / PIX_PER_THREAD;            // 8,388,608

    for (int t = tid; t < nchunks; t += stride) {
        const int p0 = t * PIX_PER_THREAD;
        const int w0 = p0 & (W_ - 1);           // W divisible by 4 -> same row
        const int h  = (p0 >> LOG_W) & (H_ - 1);
        const int n  = p0 >> LOG_HW;

        // y (row) coordinate — shared by the 4 pixels
        const float yn = (2.0f * (float)h + 1.0f) * (1.0f / (float)H_) - 1.0f;
        const float iy = ((s * yn + 1.0f) * (float)H_ - 1.0f) * 0.5f;
        const float y0f = floorf(iy);
        float wy1 = iy - y0f, wy0 = 1.0f - wy1;
        const int y0 = (int)y0f, y1 = y0 + 1;
        if (y0 < 0 || y0 > H_ - 1) wy0 = 0.0f;
        if (y1 < 0 || y1 > H_ - 1) wy1 = 0.0f;
        const int cy0 = min(max(y0, 0), H_ - 1);
        const int cy1 = min(max(y1, 0), H_ - 1);

        const float2* __restrict__ base  = in + ((size_t)n << LOG_HW);
        const float2* __restrict__ row0p = base + ((size_t)cy0 << LOG_W);
        const float2* __restrict__ row1p = base + ((size_t)cy1 << LOG_W);

        float2 res[PIX_PER_THREAD];

#pragma unroll
        for (int k = 0; k < PIX_PER_THREAD; ++k) {
            const int w = w0 + k;
            const float xn = (2.0f * (float)w + 1.0f) * (1.0f / (float)W_) - 1.0f;
            const float ix = ((s * xn + 1.0f) * (float)W_ - 1.0f) * 0.5f;
            const float x0f = floorf(ix);
            float wx1 = ix - x0f, wx0 = 1.0f - wx1;
            const int x0 = (int)x0f, x1 = x0 + 1;
            if (x0 < 0 || x0 > W_ - 1) wx0 = 0.0f;
            if (x1 < 0 || x1 > W_ - 1) wx1 = 0.0f;
            const int cx0 = min(max(x0, 0), W_ - 1);
            const int cx1 = min(max(x1, 0), W_ - 1);

            const float2 v00 = __ldg(&row0p[cx0]);
            const float2 v01 = __ldg(&row0p[cx1]);
            const float2 v10 = __ldg(&row1p[cx0]);
            const float2 v11 = __ldg(&row1p[cx1]);

            const float row0x = wx0 * v00.x + wx1 * v01.x;
            const float row0y = wx0 * v00.y + wx1 * v01.y;
            const float row1x = wx0 * v10.x + wx1 * v11.x;
            const float row1y = wx0 * v10.y + wx1 * v11.y;
            res[k].x = wy0 * row0x + wy1 * row1x;
            res[k].y = wy0 * row0y + wy1 * row1y;
        }

        float4* __restrict__ outv = (float4*)(out + p0);
        outv[0] = make_float4(res[0].x, res[0].y, res[1].x, res[1].y);
        outv[1] = make_float4(res[2].x, res[2].y, res[3].x, res[3].y);
    }
}

extern "C" void kernel_launch(void* const* d_in, const int* in_sizes, int n_in,
                              void* d_out, int out_size)
{
    const float2* in    = (const float2*)d_in[0];
    const float*  theta = (const float*)d_in[1];
    float2*       out   = (float2*)d_out;

    complex_scaling_kernel<<<BLOCKS, THREADS>>>(in, theta, out);
}